// round 1
// baseline (speedup 1.0000x reference)
#include <cuda_runtime.h>
#include <cuda_bf16.h>
#include <cstdint>

// ---------------- problem sizes ----------------
#define N_SRC0 200000
#define N_DST0 50000
#define N_DST1 10000
#define E0     800000
#define E1     160000
#define D      128

// ---------------- scratch (device globals; no allocs allowed) ----------------
__device__ float g_h0[(size_t)N_SRC0 * D];    // relu(feat@Wi+bi)
__device__ float g_h1[(size_t)N_DST0 * D];    // layer0 output
__device__ float g_hn0[(size_t)N_DST0 * D];   // mean-aggregated neighbors L0
__device__ float g_hn1[(size_t)N_DST1 * D];   // mean-aggregated neighbors L1
__device__ float g_dWi[D * 256];              // duplicated weights
__device__ float g_dWs[D * 256];
__device__ float g_dWn[D * 256];
__device__ int g_deg0[N_DST0], g_rp0[N_DST0], g_cur0[N_DST0];
__device__ int g_deg1[N_DST1], g_rp1[N_DST1], g_cur1[N_DST1];
__device__ int g_es0[E0], g_es1[E1];

// packed f32x2 FMA (sm_103a)
#define FFMA2(acc, a, b) \
    asm volatile("fma.rn.f32x2 %0, %1, %2, %0;" : "+l"(acc) : "l"(a), "l"(b))

// ---------------- weight duplication ----------------
// dup layout per k-row (256 floats): position p = 64q + 4c + r  (q=0..3, c=0..15, r=0..3)
// holds W[k][32q + 2c + (r>>1)]  -> each aligned 16B chunk is ((w,w),(w',w')) so a
// single conflict-free LDS.128 yields two broadcast-packed f32x2 multiplier pairs.
__global__ void dup_kernel(const float* __restrict__ W, float* __restrict__ dW) {
    int idx = blockIdx.x * blockDim.x + threadIdx.x;   // 0..32767
    int k = idx >> 8;
    int p = idx & 255;
    int col = ((p >> 6) << 5) + (((p & 63) >> 2) << 1) + ((p & 3) >> 1);
    dW[idx] = W[(k << 7) + col];
}

// ---------------- fused SGEMM: out = act( A0@W0 [+ A1@W1] + b0 [+ b1] ) ----------------
// BM=128, BN=128, BK=16, 256 threads, thread tile 8 rows x 8 cols, f32x2 accumulators
template <bool RELU, bool DUAL>
__global__ void __launch_bounds__(256)
gemm_kernel(const float* __restrict__ A0, const float* __restrict__ dW0,
            const float* __restrict__ A1, const float* __restrict__ dW1,
            const float* __restrict__ b0, const float* __restrict__ b1,
            float* __restrict__ out, int M)
{
    __shared__ __align__(16) float As[16][128];
    __shared__ __align__(16) float Ws[16][256];

    const int tid = threadIdx.x;
    const int rg = tid >> 4;    // 0..15 -> rows rg*8..rg*8+7
    const int cg = tid & 15;    // 0..15 -> cols {32q + 2cg + s}
    const int rowBase = blockIdx.x * 128;

    unsigned long long acc[4][8];
#pragma unroll
    for (int i = 0; i < 4; i++)
#pragma unroll
        for (int j = 0; j < 8; j++) acc[i][j] = 0ull;

    const int npass = DUAL ? 2 : 1;
    for (int pass = 0; pass < npass; ++pass) {
        const float* A = (pass == 0) ? A0 : A1;
        const float* W = (pass == 0) ? dW0 : dW1;
#pragma unroll 1
        for (int kt = 0; kt < 8; ++kt) {
            // A tile: 128 rows x 16 k (store transposed [k][row])
#pragma unroll
            for (int l = 0; l < 2; l++) {
                int idx = tid + 256 * l;        // 0..511
                int ar = idx >> 2;              // 0..127
                int ak = (idx & 3) << 2;        // 0,4,8,12
                int grow = rowBase + ar;
                float4 v = make_float4(0.f, 0.f, 0.f, 0.f);
                if (grow < M)
                    v = *reinterpret_cast<const float4*>(A + (size_t)grow * D + kt * 16 + ak);
                As[ak + 0][ar] = v.x;
                As[ak + 1][ar] = v.y;
                As[ak + 2][ar] = v.z;
                As[ak + 3][ar] = v.w;
            }
            // W tile (duplicated layout): 16 x 256
#pragma unroll
            for (int l = 0; l < 4; l++) {
                int idx = tid + 256 * l;        // 0..1023
                int wk = idx >> 6;              // 0..15
                int wp = (idx & 63) << 2;       // 0..252
                *reinterpret_cast<float4*>(&Ws[wk][wp]) =
                    *reinterpret_cast<const float4*>(W + (size_t)(kt * 16 + wk) * 256 + wp);
            }
            __syncthreads();
#pragma unroll
            for (int kk = 0; kk < 16; ++kk) {
                unsigned long long a2[4], w2[8];
                const ulonglong2* ap =
                    reinterpret_cast<const ulonglong2*>(&As[kk][rg * 8]);
                ulonglong2 t0 = ap[0], t1 = ap[1];
                a2[0] = t0.x; a2[1] = t0.y; a2[2] = t1.x; a2[3] = t1.y;
#pragma unroll
                for (int q = 0; q < 4; q++) {
                    ulonglong2 w =
                        *reinterpret_cast<const ulonglong2*>(&Ws[kk][q * 64 + cg * 4]);
                    w2[2 * q] = w.x;
                    w2[2 * q + 1] = w.y;
                }
#pragma unroll
                for (int i = 0; i < 4; i++)
#pragma unroll
                    for (int j = 0; j < 8; j++) FFMA2(acc[i][j], a2[i], w2[j]);
            }
            __syncthreads();
        }
    }

    // epilogue: bias + act + coalesced float2 stores
    float bias[8];
#pragma unroll
    for (int j = 0; j < 8; j++) {
        int col = ((j >> 1) << 5) + (cg << 1) + (j & 1);
        float b = b0[col];
        if (DUAL) b += b1[col];
        bias[j] = b;
    }
#pragma unroll
    for (int i = 0; i < 4; i++) {
#pragma unroll
        for (int h = 0; h < 2; h++) {
            int r = rowBase + rg * 8 + 2 * i + h;
            if (r < M) {
#pragma unroll
                for (int q = 0; q < 4; q++) {
                    float2 p0 = *reinterpret_cast<float2*>(&acc[i][2 * q]);
                    float2 p1 = *reinterpret_cast<float2*>(&acc[i][2 * q + 1]);
                    float vx = (h ? p0.y : p0.x) + bias[2 * q];
                    float vy = (h ? p1.y : p1.x) + bias[2 * q + 1];
                    if (RELU) {
                        vx = fmaxf(vx, 0.f);
                        vy = fmaxf(vy, 0.f);
                    }
                    *reinterpret_cast<float2*>(out + (size_t)r * D + q * 32 + cg * 2) =
                        make_float2(vx, vy);
                }
            }
        }
    }
}

// ---------------- graph CSR build + mean aggregation ----------------
__global__ void hist_kernel(const int* __restrict__ dst, int* __restrict__ deg, int E) {
    int e = blockIdx.x * blockDim.x + threadIdx.x;
    if (e < E) atomicAdd(&deg[dst[e]], 1);
}

__global__ void scan_kernel(const int* __restrict__ deg, int* __restrict__ rp,
                            int* __restrict__ cur, int n) {
    __shared__ int sp[1024];
    int t = threadIdx.x;
    int chunk = (n + 1023) >> 10;
    int s = t * chunk;
    int e = min(n, s + chunk);
    int sum = 0;
    for (int i = s; i < e; i++) sum += deg[i];
    sp[t] = sum;
    __syncthreads();
    for (int off = 1; off < 1024; off <<= 1) {
        int v = (t >= off) ? sp[t - off] : 0;
        __syncthreads();
        sp[t] += v;
        __syncthreads();
    }
    int base = (t > 0) ? sp[t - 1] : 0;
    for (int i = s; i < e; i++) {
        rp[i] = base;
        cur[i] = base;
        base += deg[i];
    }
}

__global__ void fill_kernel(const int* __restrict__ src, const int* __restrict__ dst,
                            int* __restrict__ cur, int* __restrict__ es, int E) {
    int e = blockIdx.x * blockDim.x + threadIdx.x;
    if (e < E) {
        int p = atomicAdd(&cur[dst[e]], 1);
        es[p] = src[e];
    }
}

// one warp per dst node; edge indices fetched 32-wide then broadcast via shfl
__global__ void agg_kernel(const float* __restrict__ h, const int* __restrict__ rp,
                           const int* __restrict__ deg, const int* __restrict__ es,
                           float* __restrict__ hn, int ndst) {
    int lane = threadIdx.x & 31;
    int w = (blockIdx.x * blockDim.x + threadIdx.x) >> 5;
    if (w >= ndst) return;
    int start = rp[w];
    int cnt = deg[w];
    float4 acc = make_float4(0.f, 0.f, 0.f, 0.f);
    const float4* h4 = reinterpret_cast<const float4*>(h);
    for (int base = 0; base < cnt; base += 32) {
        int n = min(32, cnt - base);
        int sidx = (lane < n) ? es[start + base + lane] : 0;
        for (int j = 0; j < n; j++) {
            int s = __shfl_sync(0xffffffffu, sidx, j);
            float4 v = h4[(size_t)s * 32 + lane];
            acc.x += v.x; acc.y += v.y; acc.z += v.z; acc.w += v.w;
        }
    }
    float inv = 1.0f / (float)max(cnt, 1);
    reinterpret_cast<float4*>(hn)[(size_t)w * 32 + lane] =
        make_float4(acc.x * inv, acc.y * inv, acc.z * inv, acc.w * inv);
}

// ---------------- launch ----------------
extern "C" void kernel_launch(void* const* d_in, const int* in_sizes, int n_in,
                              void* d_out, int out_size) {
    const float* feat   = (const float*)d_in[0];
    const int*   src0   = (const int*)d_in[1];
    const int*   dst0   = (const int*)d_in[2];
    const int*   src1   = (const int*)d_in[3];
    const int*   dst1   = (const int*)d_in[4];
    const float* W_init = (const float*)d_in[5];
    const float* b_init = (const float*)d_in[6];
    const float* W_self = (const float*)d_in[7];
    const float* b_self = (const float*)d_in[8];
    const float* W_neigh= (const float*)d_in[9];
    const float* b_neigh= (const float*)d_in[10];
    float* out = (float*)d_out;

    float *h0, *h1, *hn0, *hn1, *dWi, *dWs, *dWn;
    int *deg0, *rp0, *cur0, *es0, *deg1, *rp1, *cur1, *es1;
    cudaGetSymbolAddress((void**)&h0,  g_h0);
    cudaGetSymbolAddress((void**)&h1,  g_h1);
    cudaGetSymbolAddress((void**)&hn0, g_hn0);
    cudaGetSymbolAddress((void**)&hn1, g_hn1);
    cudaGetSymbolAddress((void**)&dWi, g_dWi);
    cudaGetSymbolAddress((void**)&dWs, g_dWs);
    cudaGetSymbolAddress((void**)&dWn, g_dWn);
    cudaGetSymbolAddress((void**)&deg0, g_deg0);
    cudaGetSymbolAddress((void**)&rp0,  g_rp0);
    cudaGetSymbolAddress((void**)&cur0, g_cur0);
    cudaGetSymbolAddress((void**)&es0,  g_es0);
    cudaGetSymbolAddress((void**)&deg1, g_deg1);
    cudaGetSymbolAddress((void**)&rp1,  g_rp1);
    cudaGetSymbolAddress((void**)&cur1, g_cur1);
    cudaGetSymbolAddress((void**)&es1,  g_es1);

    // duplicated weight layouts
    dup_kernel<<<128, 256>>>(W_init, dWi);
    dup_kernel<<<128, 256>>>(W_self, dWs);
    dup_kernel<<<128, 256>>>(W_neigh, dWn);

    // h0 = relu(feat @ Wi + bi)
    gemm_kernel<true, false><<<(N_SRC0 + 127) / 128, 256>>>(
        feat, dWi, nullptr, nullptr, b_init, nullptr, h0, N_SRC0);

    // layer 0 graph: CSR build + mean aggregate
    cudaMemsetAsync(deg0, 0, N_DST0 * sizeof(int), 0);
    hist_kernel<<<(E0 + 255) / 256, 256>>>(dst0, deg0, E0);
    scan_kernel<<<1, 1024>>>(deg0, rp0, cur0, N_DST0);
    fill_kernel<<<(E0 + 255) / 256, 256>>>(src0, dst0, cur0, es0, E0);
    agg_kernel<<<N_DST0 / 8, 256>>>(h0, rp0, deg0, es0, hn0, N_DST0);

    // h1 = relu(h0[:50000] @ Ws + hn0 @ Wn + bs + bn)
    gemm_kernel<true, true><<<(N_DST0 + 127) / 128, 256>>>(
        h0, dWs, hn0, dWn, b_self, b_neigh, h1, N_DST0);

    // layer 1 graph
    cudaMemsetAsync(deg1, 0, N_DST1 * sizeof(int), 0);
    hist_kernel<<<(E1 + 255) / 256, 256>>>(dst1, deg1, E1);
    scan_kernel<<<1, 1024>>>(deg1, rp1, cur1, N_DST1);
    fill_kernel<<<(E1 + 255) / 256, 256>>>(src1, dst1, cur1, es1, E1);
    agg_kernel<<<N_DST1 / 8, 256>>>(h1, rp1, deg1, es1, hn1, N_DST1);

    // out = h1[:10000] @ Ws + hn1 @ Wn + bs + bn  (no relu)
    gemm_kernel<false, true><<<(N_DST1 + 127) / 128, 256>>>(
        h1, dWs, hn1, dWn, b_self, b_neigh, out, N_DST1);
}

// round 3
// speedup vs baseline: 1.7201x; 1.7201x over previous
#include <cuda_runtime.h>
#include <cuda_bf16.h>
#include <cstdint>

// ---------------- problem sizes ----------------
#define N_SRC0 200000
#define N_DST0 50000
#define N_DST1 10000
#define E0     800000
#define E1     160000
#define D      128

// ---------------- scratch (device globals; no allocs allowed) ----------------
__device__ float g_h0[(size_t)N_SRC0 * D];
__device__ float g_h1[(size_t)N_DST0 * D];
__device__ float g_hn0[(size_t)N_DST0 * D];
__device__ float g_hn1[(size_t)N_DST1 * D];
// transposed bf16 weight images Wt[n][k] = W[k][n], hi/lo split
__device__ __align__(16) __nv_bfloat16 g_WiH[16384], g_WiL[16384];
__device__ __align__(16) __nv_bfloat16 g_WsH[16384], g_WsL[16384];
__device__ __align__(16) __nv_bfloat16 g_WnH[16384], g_WnL[16384];
__device__ int g_deg0[N_DST0], g_rp0[N_DST0], g_cur0[N_DST0];
__device__ int g_deg1[N_DST1], g_rp1[N_DST1], g_cur1[N_DST1];
__device__ int g_es0[E0], g_es1[E1];

// ---------------- helpers ----------------
__device__ __forceinline__ uint32_t smem_to_u32(const void* p) {
    uint32_t a;
    asm("{ .reg .u64 t; cvta.to.shared.u64 t, %1; cvt.u32.u64 %0, t; }" : "=r"(a) : "l"(p));
    return a;
}

#define LDMATRIX_X4(r0, r1, r2, r3, addr) \
    asm volatile("ldmatrix.sync.aligned.m8n8.x4.shared.b16 {%0,%1,%2,%3}, [%4];" \
                 : "=r"(r0), "=r"(r1), "=r"(r2), "=r"(r3) : "r"(addr))

#define MMA_BF16(d, a, bv0, bv1) \
    asm volatile("mma.sync.aligned.m16n8k16.row.col.f32.bf16.bf16.f32 " \
                 "{%0,%1,%2,%3}, {%4,%5,%6,%7}, {%8,%9}, {%0,%1,%2,%3};" \
                 : "+f"((d)[0]), "+f"((d)[1]), "+f"((d)[2]), "+f"((d)[3]) \
                 : "r"((a)[0]), "r"((a)[1]), "r"((a)[2]), "r"((a)[3]), \
                   "r"(bv0), "r"(bv1))

// ---------------- weight image prep (tiny, once per launch) ----------------
// Wt[n][k] = W[k][n], split into bf16 hi/lo
__global__ void wprep_kernel(const float* __restrict__ W, __nv_bfloat16* __restrict__ H,
                             __nv_bfloat16* __restrict__ L) {
    int idx = blockIdx.x * blockDim.x + threadIdx.x;  // 0..16383
    int n = idx >> 7, k = idx & 127;
    float w = W[k * 128 + n];
    __nv_bfloat16 h = __float2bfloat16(w);
    __nv_bfloat16 l = __float2bfloat16(w - __bfloat162float(h));
    H[idx] = h;
    L[idx] = l;
}

// ---------------- mma.sync GEMM: out = act(A0@W0 [+ A1@W1] + b0 [+ b1]) ----------------
// BM=64, BN=128, K=128 fully staged; 8 warps in 2(m) x 4(n); warp tile 32x32.
// padded smem stride 136 halves -> bank(row word) = 4*row mod 32 -> conflict-free ldmatrix
#define SA 136
#define OFF_BIAS 0
#define OFF_AH   512
#define OFF_AL   (OFF_AH + 64 * SA * 2)     // 17920
#define OFF_WH   (OFF_AL + 64 * SA * 2)     // 35328
#define OFF_WL   (OFF_WH + 128 * SA * 2)    // 70144
#define SMEM_TOTAL (OFF_WL + 128 * SA * 2)  // 104960

template <bool RELU, bool DUAL>
__global__ void __launch_bounds__(256, 2)
gemm_mma(const float* __restrict__ A0, const float* __restrict__ A1,
         const __nv_bfloat16* __restrict__ W0h, const __nv_bfloat16* __restrict__ W0l,
         const __nv_bfloat16* __restrict__ W1h, const __nv_bfloat16* __restrict__ W1l,
         const float* __restrict__ b0, const float* __restrict__ b1,
         float* __restrict__ out, int M)
{
    extern __shared__ char smem[];
    float* sbias = reinterpret_cast<float*>(smem + OFF_BIAS);
    const uint32_t sb = smem_to_u32(smem);
    const int tid = threadIdx.x;
    const int wid = tid >> 5;
    const int lane = tid & 31;
    const int warp_m = wid & 1;       // 2 warps over M (32 rows each)
    const int warp_n = wid >> 1;      // 4 warps over N (32 cols each)
    const int rowBase = blockIdx.x * 64;

    if (tid < 128) {
        float b = b0[tid];
        if (DUAL) b += b1[tid];
        sbias[tid] = b;
    }

    float acc[2][4][4];
#pragma unroll
    for (int i = 0; i < 2; i++)
#pragma unroll
        for (int j = 0; j < 4; j++)
#pragma unroll
            for (int r = 0; r < 4; r++) acc[i][j][r] = 0.f;

    // per-lane ldmatrix base offsets (bytes into each image)
    const int tl = lane >> 3, trow = lane & 7;
    uint32_t aoff[2], boff[2];
#pragma unroll
    for (int mi = 0; mi < 2; mi++) {
        int row = warp_m * 32 + mi * 16 + trow + (tl & 1) * 8;
        int col = (tl >> 1) * 8;
        aoff[mi] = (uint32_t)(row * SA + col) * 2;
    }
#pragma unroll
    for (int nh = 0; nh < 2; nh++) {
        int n = warp_n * 32 + nh * 16 + (tl >> 1) * 8 + trow;
        int col = (tl & 1) * 8;
        boff[nh] = (uint32_t)(n * SA + col) * 2;
    }

    const int npass = DUAL ? 2 : 1;
#pragma unroll 1
    for (int pass = 0; pass < npass; ++pass) {
        const float* A = pass ? A1 : A0;
        const __nv_bfloat16* Wh = pass ? W1h : W0h;
        const __nv_bfloat16* Wl = pass ? W1l : W0l;

        // stage W images (128 x 128 halves -> padded smem)
        {
            const uint4* gh = reinterpret_cast<const uint4*>(Wh);
            const uint4* gl = reinterpret_cast<const uint4*>(Wl);
#pragma unroll
            for (int it = 0; it < 8; it++) {
                int idx = it * 256 + tid;        // uint4 index, 0..2047
                int r = idx >> 4, wg = idx & 15;
                uint32_t d = (uint32_t)(r * SA + wg * 8) * 2;
                *reinterpret_cast<uint4*>(smem + OFF_WH + d) = gh[idx];
                *reinterpret_cast<uint4*>(smem + OFF_WL + d) = gl[idx];
            }
        }
        // stage A panel (64 rows x 128 fp32 -> bf16 hi/lo padded smem)
#pragma unroll
        for (int it = 0; it < 8; it++) {
            int e = it * 256 + tid;              // float4 index, 0..2047
            int row = e >> 5, c4 = e & 31;
            int grow = rowBase + row;
            float4 v = make_float4(0.f, 0.f, 0.f, 0.f);
            if (grow < M)
                v = *reinterpret_cast<const float4*>(A + (size_t)grow * D + c4 * 4);
            __nv_bfloat162 h01 = __float22bfloat162_rn(make_float2(v.x, v.y));
            __nv_bfloat162 h23 = __float22bfloat162_rn(make_float2(v.z, v.w));
            float2 f01 = __bfloat1622float2(h01);
            float2 f23 = __bfloat1622float2(h23);
            __nv_bfloat162 l01 = __float22bfloat162_rn(make_float2(v.x - f01.x, v.y - f01.y));
            __nv_bfloat162 l23 = __float22bfloat162_rn(make_float2(v.z - f23.x, v.w - f23.y));
            uint32_t d = (uint32_t)(row * SA + c4 * 4) * 2;
            uint2 hw, lw;
            hw.x = *reinterpret_cast<uint32_t*>(&h01);
            hw.y = *reinterpret_cast<uint32_t*>(&h23);
            lw.x = *reinterpret_cast<uint32_t*>(&l01);
            lw.y = *reinterpret_cast<uint32_t*>(&l23);
            *reinterpret_cast<uint2*>(smem + OFF_AH + d) = hw;
            *reinterpret_cast<uint2*>(smem + OFF_AL + d) = lw;
        }
        __syncthreads();

        // main mma loop over k-steps
#pragma unroll
        for (int ks = 0; ks < 8; ks++) {
            const uint32_t kb = ks * 32;   // 16 halves per k-step
            uint32_t bh[8], bl[8];
            LDMATRIX_X4(bh[0], bh[1], bh[2], bh[3], sb + OFF_WH + boff[0] + kb);
            LDMATRIX_X4(bh[4], bh[5], bh[6], bh[7], sb + OFF_WH + boff[1] + kb);
            LDMATRIX_X4(bl[0], bl[1], bl[2], bl[3], sb + OFF_WL + boff[0] + kb);
            LDMATRIX_X4(bl[4], bl[5], bl[6], bl[7], sb + OFF_WL + boff[1] + kb);
#pragma unroll
            for (int mi = 0; mi < 2; mi++) {
                uint32_t ah[4], al[4];
                LDMATRIX_X4(ah[0], ah[1], ah[2], ah[3], sb + OFF_AH + aoff[mi] + kb);
                LDMATRIX_X4(al[0], al[1], al[2], al[3], sb + OFF_AL + aoff[mi] + kb);
#pragma unroll
                for (int nj = 0; nj < 4; nj++) {
                    uint32_t b0v = bh[(nj >> 1) * 4 + (nj & 1) * 2];
                    uint32_t b1v = bh[(nj >> 1) * 4 + (nj & 1) * 2 + 1];
                    uint32_t c0v = bl[(nj >> 1) * 4 + (nj & 1) * 2];
                    uint32_t c1v = bl[(nj >> 1) * 4 + (nj & 1) * 2 + 1];
                    MMA_BF16(acc[mi][nj], ah, b0v, b1v);   // Ah * Wh
                    MMA_BF16(acc[mi][nj], al, b0v, b1v);   // Al * Wh
                    MMA_BF16(acc[mi][nj], ah, c0v, c1v);   // Ah * Wl
                }
            }
        }
        __syncthreads();
    }

    // epilogue: bias + act + stores
    const int g = lane >> 2, t = lane & 3;
#pragma unroll
    for (int mi = 0; mi < 2; mi++) {
        int row0 = rowBase + warp_m * 32 + mi * 16 + g;
        int row1 = row0 + 8;
#pragma unroll
        for (int nj = 0; nj < 4; nj++) {
            int col = warp_n * 32 + nj * 8 + t * 2;
            float bx = sbias[col], by = sbias[col + 1];
            float2 v0 = make_float2(acc[mi][nj][0] + bx, acc[mi][nj][1] + by);
            float2 v1 = make_float2(acc[mi][nj][2] + bx, acc[mi][nj][3] + by);
            if (RELU) {
                v0.x = fmaxf(v0.x, 0.f); v0.y = fmaxf(v0.y, 0.f);
                v1.x = fmaxf(v1.x, 0.f); v1.y = fmaxf(v1.y, 0.f);
            }
            if (row0 < M)
                *reinterpret_cast<float2*>(out + (size_t)row0 * D + col) = v0;
            if (row1 < M)
                *reinterpret_cast<float2*>(out + (size_t)row1 * D + col) = v1;
        }
    }
}

// ---------------- graph CSR build + mean aggregation ----------------
__global__ void hist_kernel(const int* __restrict__ dst, int* __restrict__ deg, int E) {
    int e = blockIdx.x * blockDim.x + threadIdx.x;
    if (e < E) atomicAdd(&deg[dst[e]], 1);
}

__global__ void scan_kernel(const int* __restrict__ deg, int* __restrict__ rp,
                            int* __restrict__ cur, int n) {
    __shared__ int sp[1024];
    int t = threadIdx.x;
    int chunk = (n + 1023) >> 10;
    int s = t * chunk;
    int e = min(n, s + chunk);
    int sum = 0;
    for (int i = s; i < e; i++) sum += deg[i];
    sp[t] = sum;
    __syncthreads();
    for (int off = 1; off < 1024; off <<= 1) {
        int v = (t >= off) ? sp[t - off] : 0;
        __syncthreads();
        sp[t] += v;
        __syncthreads();
    }
    int base = (t > 0) ? sp[t - 1] : 0;
    for (int i = s; i < e; i++) {
        rp[i] = base;
        cur[i] = base;
        base += deg[i];
    }
}

__global__ void fill_kernel(const int* __restrict__ src, const int* __restrict__ dst,
                            int* __restrict__ cur, int* __restrict__ es, int E) {
    int e = blockIdx.x * blockDim.x + threadIdx.x;
    if (e < E) {
        int p = atomicAdd(&cur[dst[e]], 1);
        es[p] = src[e];
    }
}

// one warp per dst node; edge indices fetched 32-wide then broadcast via shfl
__global__ void agg_kernel(const float* __restrict__ h, const int* __restrict__ rp,
                           const int* __restrict__ deg, const int* __restrict__ es,
                           float* __restrict__ hn, int ndst) {
    int lane = threadIdx.x & 31;
    int w = (blockIdx.x * blockDim.x + threadIdx.x) >> 5;
    if (w >= ndst) return;
    int start = rp[w];
    int cnt = deg[w];
    float4 acc = make_float4(0.f, 0.f, 0.f, 0.f);
    const float4* h4 = reinterpret_cast<const float4*>(h);
    for (int base = 0; base < cnt; base += 32) {
        int n = min(32, cnt - base);
        int sidx = (lane < n) ? es[start + base + lane] : 0;
        for (int j = 0; j < n; j++) {
            int s = __shfl_sync(0xffffffffu, sidx, j);
            float4 v = h4[(size_t)s * 32 + lane];
            acc.x += v.x; acc.y += v.y; acc.z += v.z; acc.w += v.w;
        }
    }
    float inv = 1.0f / (float)max(cnt, 1);
    reinterpret_cast<float4*>(hn)[(size_t)w * 32 + lane] =
        make_float4(acc.x * inv, acc.y * inv, acc.z * inv, acc.w * inv);
}

// ---------------- launch ----------------
extern "C" void kernel_launch(void* const* d_in, const int* in_sizes, int n_in,
                              void* d_out, int out_size) {
    const float* feat    = (const float*)d_in[0];
    const int*   src0    = (const int*)d_in[1];
    const int*   dst0    = (const int*)d_in[2];
    const int*   src1    = (const int*)d_in[3];
    const int*   dst1    = (const int*)d_in[4];
    const float* W_init  = (const float*)d_in[5];
    const float* b_init  = (const float*)d_in[6];
    const float* W_self  = (const float*)d_in[7];
    const float* b_self  = (const float*)d_in[8];
    const float* W_neigh = (const float*)d_in[9];
    const float* b_neigh = (const float*)d_in[10];
    float* out = (float*)d_out;

    float *h0, *h1, *hn0, *hn1;
    __nv_bfloat16 *WiH, *WiL, *WsH, *WsL, *WnH, *WnL;
    int *deg0, *rp0, *cur0, *es0, *deg1, *rp1, *cur1, *es1;
    cudaGetSymbolAddress((void**)&h0,  g_h0);
    cudaGetSymbolAddress((void**)&h1,  g_h1);
    cudaGetSymbolAddress((void**)&hn0, g_hn0);
    cudaGetSymbolAddress((void**)&hn1, g_hn1);
    cudaGetSymbolAddress((void**)&WiH, g_WiH);
    cudaGetSymbolAddress((void**)&WiL, g_WiL);
    cudaGetSymbolAddress((void**)&WsH, g_WsH);
    cudaGetSymbolAddress((void**)&WsL, g_WsL);
    cudaGetSymbolAddress((void**)&WnH, g_WnH);
    cudaGetSymbolAddress((void**)&WnL, g_WnL);
    cudaGetSymbolAddress((void**)&deg0, g_deg0);
    cudaGetSymbolAddress((void**)&rp0,  g_rp0);
    cudaGetSymbolAddress((void**)&cur0, g_cur0);
    cudaGetSymbolAddress((void**)&es0,  g_es0);
    cudaGetSymbolAddress((void**)&deg1, g_deg1);
    cudaGetSymbolAddress((void**)&rp1,  g_rp1);
    cudaGetSymbolAddress((void**)&cur1, g_cur1);
    cudaGetSymbolAddress((void**)&es1,  g_es1);

    cudaFuncSetAttribute(gemm_mma<true, false>,
                         cudaFuncAttributeMaxDynamicSharedMemorySize, SMEM_TOTAL);
    cudaFuncSetAttribute(gemm_mma<true, true>,
                         cudaFuncAttributeMaxDynamicSharedMemorySize, SMEM_TOTAL);
    cudaFuncSetAttribute(gemm_mma<false, true>,
                         cudaFuncAttributeMaxDynamicSharedMemorySize, SMEM_TOTAL);

    // weight images (Wt bf16 hi/lo)
    wprep_kernel<<<64, 256>>>(W_init, WiH, WiL);
    wprep_kernel<<<64, 256>>>(W_self, WsH, WsL);
    wprep_kernel<<<64, 256>>>(W_neigh, WnH, WnL);

    // h0 = relu(feat @ Wi + bi)
    gemm_mma<true, false><<<(N_SRC0 + 63) / 64, 256, SMEM_TOTAL>>>(
        feat, nullptr, WiH, WiL, nullptr, nullptr, b_init, nullptr, h0, N_SRC0);

    // layer 0 graph: CSR build + mean aggregate
    cudaMemsetAsync(deg0, 0, N_DST0 * sizeof(int), 0);
    hist_kernel<<<(E0 + 255) / 256, 256>>>(dst0, deg0, E0);
    scan_kernel<<<1, 1024>>>(deg0, rp0, cur0, N_DST0);
    fill_kernel<<<(E0 + 255) / 256, 256>>>(src0, dst0, cur0, es0, E0);
    agg_kernel<<<N_DST0 / 8, 256>>>(h0, rp0, deg0, es0, hn0, N_DST0);

    // h1 = relu(h0[:50000] @ Ws + hn0 @ Wn + bs + bn)
    gemm_mma<true, true><<<(N_DST0 + 63) / 64, 256, SMEM_TOTAL>>>(
        h0, hn0, WsH, WsL, WnH, WnL, b_self, b_neigh, h1, N_DST0);

    // layer 1 graph
    cudaMemsetAsync(deg1, 0, N_DST1 * sizeof(int), 0);
    hist_kernel<<<(E1 + 255) / 256, 256>>>(dst1, deg1, E1);
    scan_kernel<<<1, 1024>>>(deg1, rp1, cur1, N_DST1);
    fill_kernel<<<(E1 + 255) / 256, 256>>>(src1, dst1, cur1, es1, E1);
    agg_kernel<<<N_DST1 / 8, 256>>>(h1, rp1, deg1, es1, hn1, N_DST1);

    // out = h1[:10000] @ Ws + hn1 @ Wn + bs + bn  (no relu)
    gemm_mma<false, true><<<(N_DST1 + 63) / 64, 256, SMEM_TOTAL>>>(
        h1, hn1, WsH, WsL, WnH, WnL, b_self, b_neigh, out, N_DST1);
}

// round 4
// speedup vs baseline: 1.7516x; 1.0183x over previous
#include <cuda_runtime.h>
#include <cuda_bf16.h>
#include <cstdint>

// ---------------- problem sizes ----------------
#define N_SRC0 200000
#define N_DST0 50000
#define N_DST1 10000
#define E0     800000
#define E1     160000
#define D      128

// ---------------- scratch (device globals; no allocs allowed) ----------------
__device__ float g_h0[(size_t)N_SRC0 * D];
__device__ float g_h1[(size_t)N_DST0 * D];
__device__ float g_hn0[(size_t)N_DST0 * D];
__device__ float g_hn1[(size_t)N_DST1 * D];
// transposed bf16 weight images Wt[n][k] = W[k][n], hi/lo split
__device__ __align__(16) __nv_bfloat16 g_WiH[16384], g_WiL[16384];
__device__ __align__(16) __nv_bfloat16 g_WsH[16384], g_WsL[16384];
__device__ __align__(16) __nv_bfloat16 g_WnH[16384], g_WnL[16384];
__device__ int g_deg0[N_DST0], g_rp0[N_DST0], g_cur0[N_DST0];
__device__ int g_deg1[N_DST1], g_rp1[N_DST1], g_cur1[N_DST1];
__device__ int g_es0[E0], g_es1[E1];

// ---------------- helpers ----------------
__device__ __forceinline__ uint32_t smem_to_u32(const void* p) {
    uint32_t a;
    asm("{ .reg .u64 t; cvta.to.shared.u64 t, %1; cvt.u32.u64 %0, t; }" : "=r"(a) : "l"(p));
    return a;
}

#define LDMATRIX_X4(r0, r1, r2, r3, addr) \
    asm volatile("ldmatrix.sync.aligned.m8n8.x4.shared.b16 {%0,%1,%2,%3}, [%4];" \
                 : "=r"(r0), "=r"(r1), "=r"(r2), "=r"(r3) : "r"(addr))

#define MMA_BF16(d, a, bv0, bv1) \
    asm volatile("mma.sync.aligned.m16n8k16.row.col.f32.bf16.bf16.f32 " \
                 "{%0,%1,%2,%3}, {%4,%5,%6,%7}, {%8,%9}, {%0,%1,%2,%3};" \
                 : "+f"((d)[0]), "+f"((d)[1]), "+f"((d)[2]), "+f"((d)[3]) \
                 : "r"((a)[0]), "r"((a)[1]), "r"((a)[2]), "r"((a)[3]), \
                   "r"(bv0), "r"(bv1))

#define CP_ASYNC16(dst, src) \
    asm volatile("cp.async.cg.shared.global [%0], [%1], 16;" :: "r"(dst), "l"(src))
#define CP_COMMIT() asm volatile("cp.async.commit_group;")
#define CP_WAIT0()  asm volatile("cp.async.wait_group 0;" ::: "memory")

// ---------------- weight image prep (one launch for all 3) ----------------
// Wt[n][k] = W[k][n], split into bf16 hi/lo
__global__ void wprep_kernel(const float* __restrict__ Wi, const float* __restrict__ Ws,
                             const float* __restrict__ Wn,
                             __nv_bfloat16* __restrict__ WiH, __nv_bfloat16* __restrict__ WiL,
                             __nv_bfloat16* __restrict__ WsH, __nv_bfloat16* __restrict__ WsL,
                             __nv_bfloat16* __restrict__ WnH, __nv_bfloat16* __restrict__ WnL) {
    int bid = blockIdx.x;
    const float* W = (bid < 64) ? Wi : (bid < 128) ? Ws : Wn;
    __nv_bfloat16* H = (bid < 64) ? WiH : (bid < 128) ? WsH : WnH;
    __nv_bfloat16* L = (bid < 64) ? WiL : (bid < 128) ? WsL : WnL;
    int idx = (bid & 63) * 256 + threadIdx.x;   // 0..16383
    int n = idx >> 7, k = idx & 127;
    float w = W[k * 128 + n];
    __nv_bfloat16 h = __float2bfloat16(w);
    __nv_bfloat16 l = __float2bfloat16(w - __bfloat162float(h));
    H[idx] = h;
    L[idx] = l;
}

// ---------------- mma.sync GEMM: out = act(A0@W0 [+ A1@W1] + b0 [+ b1]) ----------------
// BM=64, BN=128, K=128 fully staged; 4 warps in 2(m) x 2(n); warp tile 32x64.
// padded smem stride 136 halves -> conflict-free ldmatrix
#define SA 136
#define OFF_BIAS 0
#define OFF_AH   512
#define OFF_AL   (OFF_AH + 64 * SA * 2)     // 17920
#define OFF_WH   (OFF_AL + 64 * SA * 2)     // 35328
#define OFF_WL   (OFF_WH + 128 * SA * 2)    // 70144
#define SMEM_TOTAL (OFF_WL + 128 * SA * 2)  // 104960

template <bool RELU, bool DUAL>
__global__ void __launch_bounds__(128)
gemm_mma(const float* __restrict__ A0, const float* __restrict__ A1,
         const __nv_bfloat16* __restrict__ W0h, const __nv_bfloat16* __restrict__ W0l,
         const __nv_bfloat16* __restrict__ W1h, const __nv_bfloat16* __restrict__ W1l,
         const float* __restrict__ b0, const float* __restrict__ b1,
         float* __restrict__ out, int M)
{
    extern __shared__ char smem[];
    float* sbias = reinterpret_cast<float*>(smem + OFF_BIAS);
    const uint32_t sb = smem_to_u32(smem);
    const int tid = threadIdx.x;
    const int wid = tid >> 5;
    const int lane = tid & 31;
    const int warp_m = wid & 1;       // 2 warps over M (32 rows each)
    const int warp_n = wid >> 1;      // 2 warps over N (64 cols each)
    const int rowBase = blockIdx.x * 64;

    if (tid < 128) {
        float b = b0[tid];
        if (DUAL) b += b1[tid];
        sbias[tid] = b;
    }

    float acc[2][8][4];
#pragma unroll
    for (int i = 0; i < 2; i++)
#pragma unroll
        for (int j = 0; j < 8; j++)
#pragma unroll
            for (int r = 0; r < 4; r++) acc[i][j][r] = 0.f;

    // per-lane ldmatrix base offsets (bytes)
    const int tl = lane >> 3, trow = lane & 7;
    uint32_t aoff[2], boff[4];
#pragma unroll
    for (int mi = 0; mi < 2; mi++) {
        int row = warp_m * 32 + mi * 16 + trow + (tl & 1) * 8;
        int col = (tl >> 1) * 8;
        aoff[mi] = (uint32_t)(row * SA + col) * 2;
    }
#pragma unroll
    for (int nh = 0; nh < 4; nh++) {
        int n = warp_n * 64 + nh * 16 + (tl >> 1) * 8 + trow;
        int col = (tl & 1) * 8;
        boff[nh] = (uint32_t)(n * SA + col) * 2;
    }

    const int npass = DUAL ? 2 : 1;
#pragma unroll 1
    for (int pass = 0; pass < npass; ++pass) {
        const float* A = pass ? A1 : A0;
        const __nv_bfloat16* Wh = pass ? W1h : W0h;
        const __nv_bfloat16* Wl = pass ? W1l : W0l;

        // stage W images via cp.async (pure copy, overlaps with A convert below)
        {
            const uint4* gh = reinterpret_cast<const uint4*>(Wh);
            const uint4* gl = reinterpret_cast<const uint4*>(Wl);
#pragma unroll
            for (int it = 0; it < 16; it++) {
                int idx = it * 128 + tid;        // uint4 index, 0..2047
                int r = idx >> 4, wg = idx & 15;
                uint32_t d = (uint32_t)(r * SA + wg * 8) * 2;
                CP_ASYNC16(sb + OFF_WH + d, gh + idx);
                CP_ASYNC16(sb + OFF_WL + d, gl + idx);
            }
            CP_COMMIT();
        }
        // stage A panel (64 rows x 128 fp32 -> bf16 hi/lo padded smem)
#pragma unroll
        for (int it = 0; it < 16; it++) {
            int e = it * 128 + tid;              // float4 index, 0..2047
            int row = e >> 5, c4 = e & 31;
            int grow = rowBase + row;
            float4 v = make_float4(0.f, 0.f, 0.f, 0.f);
            if (grow < M)
                v = *reinterpret_cast<const float4*>(A + (size_t)grow * D + c4 * 4);
            __nv_bfloat162 h01 = __float22bfloat162_rn(make_float2(v.x, v.y));
            __nv_bfloat162 h23 = __float22bfloat162_rn(make_float2(v.z, v.w));
            float2 f01 = __bfloat1622float2(h01);
            float2 f23 = __bfloat1622float2(h23);
            __nv_bfloat162 l01 = __float22bfloat162_rn(make_float2(v.x - f01.x, v.y - f01.y));
            __nv_bfloat162 l23 = __float22bfloat162_rn(make_float2(v.z - f23.x, v.w - f23.y));
            uint32_t d = (uint32_t)(row * SA + c4 * 4) * 2;
            uint2 hw, lw;
            hw.x = *reinterpret_cast<uint32_t*>(&h01);
            hw.y = *reinterpret_cast<uint32_t*>(&h23);
            lw.x = *reinterpret_cast<uint32_t*>(&l01);
            lw.y = *reinterpret_cast<uint32_t*>(&l23);
            *reinterpret_cast<uint2*>(smem + OFF_AH + d) = hw;
            *reinterpret_cast<uint2*>(smem + OFF_AL + d) = lw;
        }
        CP_WAIT0();
        __syncthreads();

        // main mma loop over k-steps
#pragma unroll
        for (int ks = 0; ks < 8; ks++) {
            const uint32_t kb = ks * 32;   // 16 halves per k-step
            uint32_t bh[16], bl[16];
#pragma unroll
            for (int nh = 0; nh < 4; nh++) {
                LDMATRIX_X4(bh[nh * 4], bh[nh * 4 + 1], bh[nh * 4 + 2], bh[nh * 4 + 3],
                            sb + OFF_WH + boff[nh] + kb);
                LDMATRIX_X4(bl[nh * 4], bl[nh * 4 + 1], bl[nh * 4 + 2], bl[nh * 4 + 3],
                            sb + OFF_WL + boff[nh] + kb);
            }
#pragma unroll
            for (int mi = 0; mi < 2; mi++) {
                uint32_t ah[4], al[4];
                LDMATRIX_X4(ah[0], ah[1], ah[2], ah[3], sb + OFF_AH + aoff[mi] + kb);
                LDMATRIX_X4(al[0], al[1], al[2], al[3], sb + OFF_AL + aoff[mi] + kb);
#pragma unroll
                for (int nj = 0; nj < 8; nj++) {
                    int bi = (nj >> 1) * 4 + (nj & 1) * 2;
                    MMA_BF16(acc[mi][nj], ah, bh[bi], bh[bi + 1]);   // Ah * Wh
                    MMA_BF16(acc[mi][nj], al, bh[bi], bh[bi + 1]);   // Al * Wh
                    MMA_BF16(acc[mi][nj], ah, bl[bi], bl[bi + 1]);   // Ah * Wl
                }
            }
        }
        __syncthreads();
    }

    // epilogue: bias + act + stores
    const int g = lane >> 2, t = lane & 3;
#pragma unroll
    for (int mi = 0; mi < 2; mi++) {
        int row0 = rowBase + warp_m * 32 + mi * 16 + g;
        int row1 = row0 + 8;
#pragma unroll
        for (int nj = 0; nj < 8; nj++) {
            int col = warp_n * 64 + nj * 8 + t * 2;
            float bx = sbias[col], by = sbias[col + 1];
            float2 v0 = make_float2(acc[mi][nj][0] + bx, acc[mi][nj][1] + by);
            float2 v1 = make_float2(acc[mi][nj][2] + bx, acc[mi][nj][3] + by);
            if (RELU) {
                v0.x = fmaxf(v0.x, 0.f); v0.y = fmaxf(v0.y, 0.f);
                v1.x = fmaxf(v1.x, 0.f); v1.y = fmaxf(v1.y, 0.f);
            }
            if (row0 < M)
                *reinterpret_cast<float2*>(out + (size_t)row0 * D + col) = v0;
            if (row1 < M)
                *reinterpret_cast<float2*>(out + (size_t)row1 * D + col) = v1;
        }
    }
}

// ---------------- graph CSR build + mean aggregation ----------------
__global__ void hist_kernel(const int* __restrict__ dst, int* __restrict__ deg, int E) {
    int e = blockIdx.x * blockDim.x + threadIdx.x;
    if (e < E) atomicAdd(&deg[dst[e]], 1);
}

__global__ void scan_kernel(const int* __restrict__ deg, int* __restrict__ rp,
                            int* __restrict__ cur, int n) {
    __shared__ int sp[1024];
    int t = threadIdx.x;
    int chunk = (n + 1023) >> 10;
    int s = t * chunk;
    int e = min(n, s + chunk);
    int sum = 0;
    for (int i = s; i < e; i++) sum += deg[i];
    sp[t] = sum;
    __syncthreads();
    for (int off = 1; off < 1024; off <<= 1) {
        int v = (t >= off) ? sp[t - off] : 0;
        __syncthreads();
        sp[t] += v;
        __syncthreads();
    }
    int base = (t > 0) ? sp[t - 1] : 0;
    for (int i = s; i < e; i++) {
        rp[i] = base;
        cur[i] = base;
        base += deg[i];
    }
}

__global__ void fill_kernel(const int* __restrict__ src, const int* __restrict__ dst,
                            int* __restrict__ cur, int* __restrict__ es, int E) {
    int e = blockIdx.x * blockDim.x + threadIdx.x;
    if (e < E) {
        int p = atomicAdd(&cur[dst[e]], 1);
        es[p] = src[e];
    }
}

// one warp per dst node; 2-way unrolled gather with dual accumulators (2x MLP)
__global__ void agg_kernel(const float* __restrict__ h, const int* __restrict__ rp,
                           const int* __restrict__ deg, const int* __restrict__ es,
                           float* __restrict__ hn, int ndst) {
    int lane = threadIdx.x & 31;
    int w = (blockIdx.x * blockDim.x + threadIdx.x) >> 5;
    if (w >= ndst) return;
    int start = rp[w];
    int cnt = deg[w];
    float4 acc0 = make_float4(0.f, 0.f, 0.f, 0.f);
    float4 acc1 = make_float4(0.f, 0.f, 0.f, 0.f);
    const float4* h4 = reinterpret_cast<const float4*>(h);
    for (int base = 0; base < cnt; base += 32) {
        int n = min(32, cnt - base);
        int sidx = (lane < n) ? es[start + base + lane] : 0;
        int j = 0;
        for (; j + 2 <= n; j += 2) {
            int s0 = __shfl_sync(0xffffffffu, sidx, j);
            int s1 = __shfl_sync(0xffffffffu, sidx, j + 1);
            float4 v0 = h4[(size_t)s0 * 32 + lane];
            float4 v1 = h4[(size_t)s1 * 32 + lane];
            acc0.x += v0.x; acc0.y += v0.y; acc0.z += v0.z; acc0.w += v0.w;
            acc1.x += v1.x; acc1.y += v1.y; acc1.z += v1.z; acc1.w += v1.w;
        }
        if (j < n) {
            int s0 = __shfl_sync(0xffffffffu, sidx, j);
            float4 v0 = h4[(size_t)s0 * 32 + lane];
            acc0.x += v0.x; acc0.y += v0.y; acc0.z += v0.z; acc0.w += v0.w;
        }
    }
    float inv = 1.0f / (float)max(cnt, 1);
    reinterpret_cast<float4*>(hn)[(size_t)w * 32 + lane] =
        make_float4((acc0.x + acc1.x) * inv, (acc0.y + acc1.y) * inv,
                    (acc0.z + acc1.z) * inv, (acc0.w + acc1.w) * inv);
}

// ---------------- launch ----------------
extern "C" void kernel_launch(void* const* d_in, const int* in_sizes, int n_in,
                              void* d_out, int out_size) {
    const float* feat    = (const float*)d_in[0];
    const int*   src0    = (const int*)d_in[1];
    const int*   dst0    = (const int*)d_in[2];
    const int*   src1    = (const int*)d_in[3];
    const int*   dst1    = (const int*)d_in[4];
    const float* W_init  = (const float*)d_in[5];
    const float* b_init  = (const float*)d_in[6];
    const float* W_self  = (const float*)d_in[7];
    const float* b_self  = (const float*)d_in[8];
    const float* W_neigh = (const float*)d_in[9];
    const float* b_neigh = (const float*)d_in[10];
    float* out = (float*)d_out;

    float *h0, *h1, *hn0, *hn1;
    __nv_bfloat16 *WiH, *WiL, *WsH, *WsL, *WnH, *WnL;
    int *deg0, *rp0, *cur0, *es0, *deg1, *rp1, *cur1, *es1;
    cudaGetSymbolAddress((void**)&h0,  g_h0);
    cudaGetSymbolAddress((void**)&h1,  g_h1);
    cudaGetSymbolAddress((void**)&hn0, g_hn0);
    cudaGetSymbolAddress((void**)&hn1, g_hn1);
    cudaGetSymbolAddress((void**)&WiH, g_WiH);
    cudaGetSymbolAddress((void**)&WiL, g_WiL);
    cudaGetSymbolAddress((void**)&WsH, g_WsH);
    cudaGetSymbolAddress((void**)&WsL, g_WsL);
    cudaGetSymbolAddress((void**)&WnH, g_WnH);
    cudaGetSymbolAddress((void**)&WnL, g_WnL);
    cudaGetSymbolAddress((void**)&deg0, g_deg0);
    cudaGetSymbolAddress((void**)&rp0,  g_rp0);
    cudaGetSymbolAddress((void**)&cur0, g_cur0);
    cudaGetSymbolAddress((void**)&es0,  g_es0);
    cudaGetSymbolAddress((void**)&deg1, g_deg1);
    cudaGetSymbolAddress((void**)&rp1,  g_rp1);
    cudaGetSymbolAddress((void**)&cur1, g_cur1);
    cudaGetSymbolAddress((void**)&es1,  g_es1);

    cudaFuncSetAttribute(gemm_mma<true, false>,
                         cudaFuncAttributeMaxDynamicSharedMemorySize, SMEM_TOTAL);
    cudaFuncSetAttribute(gemm_mma<true, true>,
                         cudaFuncAttributeMaxDynamicSharedMemorySize, SMEM_TOTAL);
    cudaFuncSetAttribute(gemm_mma<false, true>,
                         cudaFuncAttributeMaxDynamicSharedMemorySize, SMEM_TOTAL);

    // weight images (Wt bf16 hi/lo), all three in one launch
    wprep_kernel<<<192, 256>>>(W_init, W_self, W_neigh, WiH, WiL, WsH, WsL, WnH, WnL);

    // h0 = relu(feat @ Wi + bi)
    gemm_mma<true, false><<<(N_SRC0 + 63) / 64, 128, SMEM_TOTAL>>>(
        feat, nullptr, WiH, WiL, nullptr, nullptr, b_init, nullptr, h0, N_SRC0);

    // layer 0 graph: CSR build + mean aggregate
    cudaMemsetAsync(deg0, 0, N_DST0 * sizeof(int), 0);
    hist_kernel<<<(E0 + 255) / 256, 256>>>(dst0, deg0, E0);
    scan_kernel<<<1, 1024>>>(deg0, rp0, cur0, N_DST0);
    fill_kernel<<<(E0 + 255) / 256, 256>>>(src0, dst0, cur0, es0, E0);
    agg_kernel<<<N_DST0 / 8, 256>>>(h0, rp0, deg0, es0, hn0, N_DST0);

    // h1 = relu(h0[:50000] @ Ws + hn0 @ Wn + bs + bn)
    gemm_mma<true, true><<<(N_DST0 + 63) / 64, 128, SMEM_TOTAL>>>(
        h0, hn0, WsH, WsL, WnH, WnL, b_self, b_neigh, h1, N_DST0);

    // layer 1 graph
    cudaMemsetAsync(deg1, 0, N_DST1 * sizeof(int), 0);
    hist_kernel<<<(E1 + 255) / 256, 256>>>(dst1, deg1, E1);
    scan_kernel<<<1, 1024>>>(deg1, rp1, cur1, N_DST1);
    fill_kernel<<<(E1 + 255) / 256, 256>>>(src1, dst1, cur1, es1, E1);
    agg_kernel<<<N_DST1 / 8, 256>>>(h1, rp1, deg1, es1, hn1, N_DST1);

    // out = h1[:10000] @ Ws + hn1 @ Wn + bs + bn  (no relu)
    gemm_mma<false, true><<<(N_DST1 + 63) / 64, 128, SMEM_TOTAL>>>(
        h1, hn1, WsH, WsL, WnH, WnL, b_self, b_neigh, out, N_DST1);
}

// round 5
// speedup vs baseline: 2.1954x; 1.2534x over previous
#include <cuda_runtime.h>
#include <cuda_bf16.h>
#include <cstdint>

// ---------------- problem sizes ----------------
#define N_SRC0 200000
#define N_DST0 50000
#define N_DST1 10000
#define E0     800000
#define E1     160000
#define D      128

// ---------------- scratch (device globals; no allocs allowed) ----------------
__device__ float g_h0[(size_t)N_SRC0 * D];
__device__ float g_h1[(size_t)N_DST0 * D];
__device__ float g_hn0[(size_t)N_DST0 * D];
__device__ float g_hn1[(size_t)N_DST1 * D];
// transposed bf16 weight images Wt[n][k] = W[k][n], hi/lo split
__device__ __align__(16) __nv_bfloat16 g_WiH[16384], g_WiL[16384];
__device__ __align__(16) __nv_bfloat16 g_WsH[16384], g_WsL[16384];
__device__ __align__(16) __nv_bfloat16 g_WnH[16384], g_WnL[16384];
__device__ int g_deg0[N_DST0], g_rp0[N_DST0], g_cur0[N_DST0];
__device__ int g_deg1[N_DST1], g_rp1[N_DST1], g_cur1[N_DST1];
__device__ int g_es0[E0], g_es1[E1];
__device__ int g_incl[N_DST0];       // scan temp (shared across both layers)
__device__ int g_btot[64];           // per-block totals / offsets

// ---------------- helpers ----------------
__device__ __forceinline__ uint32_t smem_to_u32(const void* p) {
    uint32_t a;
    asm("{ .reg .u64 t; cvta.to.shared.u64 t, %1; cvt.u32.u64 %0, t; }" : "=r"(a) : "l"(p));
    return a;
}

#define LDMATRIX_X4(r0, r1, r2, r3, addr) \
    asm volatile("ldmatrix.sync.aligned.m8n8.x4.shared.b16 {%0,%1,%2,%3}, [%4];" \
                 : "=r"(r0), "=r"(r1), "=r"(r2), "=r"(r3) : "r"(addr))

#define MMA_BF16(d, a, bv0, bv1) \
    asm volatile("mma.sync.aligned.m16n8k16.row.col.f32.bf16.bf16.f32 " \
                 "{%0,%1,%2,%3}, {%4,%5,%6,%7}, {%8,%9}, {%0,%1,%2,%3};" \
                 : "+f"((d)[0]), "+f"((d)[1]), "+f"((d)[2]), "+f"((d)[3]) \
                 : "r"((a)[0]), "r"((a)[1]), "r"((a)[2]), "r"((a)[3]), \
                   "r"(bv0), "r"(bv1))

#define CP_ASYNC16(dst, src) \
    asm volatile("cp.async.cg.shared.global [%0], [%1], 16;" :: "r"(dst), "l"(src))
#define CP_COMMIT() asm volatile("cp.async.commit_group;")
#define CP_WAIT0()  asm volatile("cp.async.wait_group 0;" ::: "memory")

// ---------------- weight image prep (one launch for all 3) ----------------
__global__ void wprep_kernel(const float* __restrict__ Wi, const float* __restrict__ Ws,
                             const float* __restrict__ Wn,
                             __nv_bfloat16* __restrict__ WiH, __nv_bfloat16* __restrict__ WiL,
                             __nv_bfloat16* __restrict__ WsH, __nv_bfloat16* __restrict__ WsL,
                             __nv_bfloat16* __restrict__ WnH, __nv_bfloat16* __restrict__ WnL) {
    int bid = blockIdx.x;
    const float* W = (bid < 64) ? Wi : (bid < 128) ? Ws : Wn;
    __nv_bfloat16* H = (bid < 64) ? WiH : (bid < 128) ? WsH : WnH;
    __nv_bfloat16* L = (bid < 64) ? WiL : (bid < 128) ? WsL : WnL;
    int idx = (bid & 63) * 256 + threadIdx.x;   // 0..16383
    int n = idx >> 7, k = idx & 127;
    float w = W[k * 128 + n];
    __nv_bfloat16 h = __float2bfloat16(w);
    __nv_bfloat16 l = __float2bfloat16(w - __bfloat162float(h));
    H[idx] = h;
    L[idx] = l;
}

// ---------------- mma.sync GEMM ----------------
#define SA 136
#define OFF_BIAS 0
#define OFF_AH   512
#define OFF_AL   (OFF_AH + 64 * SA * 2)
#define OFF_WH   (OFF_AL + 64 * SA * 2)
#define OFF_WL   (OFF_WH + 128 * SA * 2)
#define SMEM_TOTAL (OFF_WL + 128 * SA * 2)

template <bool RELU, bool DUAL>
__global__ void __launch_bounds__(128)
gemm_mma(const float* __restrict__ A0, const float* __restrict__ A1,
         const __nv_bfloat16* __restrict__ W0h, const __nv_bfloat16* __restrict__ W0l,
         const __nv_bfloat16* __restrict__ W1h, const __nv_bfloat16* __restrict__ W1l,
         const float* __restrict__ b0, const float* __restrict__ b1,
         float* __restrict__ out, int M)
{
    extern __shared__ char smem[];
    float* sbias = reinterpret_cast<float*>(smem + OFF_BIAS);
    const uint32_t sb = smem_to_u32(smem);
    const int tid = threadIdx.x;
    const int wid = tid >> 5;
    const int lane = tid & 31;
    const int warp_m = wid & 1;
    const int warp_n = wid >> 1;
    const int rowBase = blockIdx.x * 64;

    if (tid < 128) {
        float b = b0[tid];
        if (DUAL) b += b1[tid];
        sbias[tid] = b;
    }

    float acc[2][8][4];
#pragma unroll
    for (int i = 0; i < 2; i++)
#pragma unroll
        for (int j = 0; j < 8; j++)
#pragma unroll
            for (int r = 0; r < 4; r++) acc[i][j][r] = 0.f;

    const int tl = lane >> 3, trow = lane & 7;
    uint32_t aoff[2], boff[4];
#pragma unroll
    for (int mi = 0; mi < 2; mi++) {
        int row = warp_m * 32 + mi * 16 + trow + (tl & 1) * 8;
        int col = (tl >> 1) * 8;
        aoff[mi] = (uint32_t)(row * SA + col) * 2;
    }
#pragma unroll
    for (int nh = 0; nh < 4; nh++) {
        int n = warp_n * 64 + nh * 16 + (tl >> 1) * 8 + trow;
        int col = (tl & 1) * 8;
        boff[nh] = (uint32_t)(n * SA + col) * 2;
    }

    const int npass = DUAL ? 2 : 1;
#pragma unroll 1
    for (int pass = 0; pass < npass; ++pass) {
        const float* A = pass ? A1 : A0;
        const __nv_bfloat16* Wh = pass ? W1h : W0h;
        const __nv_bfloat16* Wl = pass ? W1l : W0l;

        {
            const uint4* gh = reinterpret_cast<const uint4*>(Wh);
            const uint4* gl = reinterpret_cast<const uint4*>(Wl);
#pragma unroll
            for (int it = 0; it < 16; it++) {
                int idx = it * 128 + tid;
                int r = idx >> 4, wg = idx & 15;
                uint32_t d = (uint32_t)(r * SA + wg * 8) * 2;
                CP_ASYNC16(sb + OFF_WH + d, gh + idx);
                CP_ASYNC16(sb + OFF_WL + d, gl + idx);
            }
            CP_COMMIT();
        }
#pragma unroll
        for (int it = 0; it < 16; it++) {
            int e = it * 128 + tid;
            int row = e >> 5, c4 = e & 31;
            int grow = rowBase + row;
            float4 v = make_float4(0.f, 0.f, 0.f, 0.f);
            if (grow < M)
                v = *reinterpret_cast<const float4*>(A + (size_t)grow * D + c4 * 4);
            __nv_bfloat162 h01 = __float22bfloat162_rn(make_float2(v.x, v.y));
            __nv_bfloat162 h23 = __float22bfloat162_rn(make_float2(v.z, v.w));
            float2 f01 = __bfloat1622float2(h01);
            float2 f23 = __bfloat1622float2(h23);
            __nv_bfloat162 l01 = __float22bfloat162_rn(make_float2(v.x - f01.x, v.y - f01.y));
            __nv_bfloat162 l23 = __float22bfloat162_rn(make_float2(v.z - f23.x, v.w - f23.y));
            uint32_t d = (uint32_t)(row * SA + c4 * 4) * 2;
            uint2 hw, lw;
            hw.x = *reinterpret_cast<uint32_t*>(&h01);
            hw.y = *reinterpret_cast<uint32_t*>(&h23);
            lw.x = *reinterpret_cast<uint32_t*>(&l01);
            lw.y = *reinterpret_cast<uint32_t*>(&l23);
            *reinterpret_cast<uint2*>(smem + OFF_AH + d) = hw;
            *reinterpret_cast<uint2*>(smem + OFF_AL + d) = lw;
        }
        CP_WAIT0();
        __syncthreads();

#pragma unroll
        for (int ks = 0; ks < 8; ks++) {
            const uint32_t kb = ks * 32;
            uint32_t bh[16], bl[16];
#pragma unroll
            for (int nh = 0; nh < 4; nh++) {
                LDMATRIX_X4(bh[nh * 4], bh[nh * 4 + 1], bh[nh * 4 + 2], bh[nh * 4 + 3],
                            sb + OFF_WH + boff[nh] + kb);
                LDMATRIX_X4(bl[nh * 4], bl[nh * 4 + 1], bl[nh * 4 + 2], bl[nh * 4 + 3],
                            sb + OFF_WL + boff[nh] + kb);
            }
#pragma unroll
            for (int mi = 0; mi < 2; mi++) {
                uint32_t ah[4], al[4];
                LDMATRIX_X4(ah[0], ah[1], ah[2], ah[3], sb + OFF_AH + aoff[mi] + kb);
                LDMATRIX_X4(al[0], al[1], al[2], al[3], sb + OFF_AL + aoff[mi] + kb);
#pragma unroll
                for (int nj = 0; nj < 8; nj++) {
                    int bi = (nj >> 1) * 4 + (nj & 1) * 2;
                    MMA_BF16(acc[mi][nj], ah, bh[bi], bh[bi + 1]);
                    MMA_BF16(acc[mi][nj], al, bh[bi], bh[bi + 1]);
                    MMA_BF16(acc[mi][nj], ah, bl[bi], bl[bi + 1]);
                }
            }
        }
        __syncthreads();
    }

    const int g = lane >> 2, t = lane & 3;
#pragma unroll
    for (int mi = 0; mi < 2; mi++) {
        int row0 = rowBase + warp_m * 32 + mi * 16 + g;
        int row1 = row0 + 8;
#pragma unroll
        for (int nj = 0; nj < 8; nj++) {
            int col = warp_n * 64 + nj * 8 + t * 2;
            float bx = sbias[col], by = sbias[col + 1];
            float2 v0 = make_float2(acc[mi][nj][0] + bx, acc[mi][nj][1] + by);
            float2 v1 = make_float2(acc[mi][nj][2] + bx, acc[mi][nj][3] + by);
            if (RELU) {
                v0.x = fmaxf(v0.x, 0.f); v0.y = fmaxf(v0.y, 0.f);
                v1.x = fmaxf(v1.x, 0.f); v1.y = fmaxf(v1.y, 0.f);
            }
            if (row0 < M)
                *reinterpret_cast<float2*>(out + (size_t)row0 * D + col) = v0;
            if (row1 < M)
                *reinterpret_cast<float2*>(out + (size_t)row1 * D + col) = v1;
        }
    }
}

// ---------------- graph CSR build + mean aggregation ----------------
__global__ void hist_kernel(const int* __restrict__ dst, int* __restrict__ deg, int E) {
    int e = blockIdx.x * blockDim.x + threadIdx.x;
    if (e < E) atomicAdd(&deg[dst[e]], 1);
}

// ---- multi-block scan: pass1 (per-block inclusive scan + block totals) ----
__global__ void scan_pass1(const int* __restrict__ deg, int* __restrict__ incl,
                           int* __restrict__ btot, int n) {
    __shared__ int wsum[32];
    int t = threadIdx.x;
    int i = blockIdx.x * 1024 + t;
    int v = (i < n) ? deg[i] : 0;
    int x = v;
#pragma unroll
    for (int o = 1; o < 32; o <<= 1) {
        int y = __shfl_up_sync(0xffffffffu, x, o);
        if ((t & 31) >= o) x += y;
    }
    if ((t & 31) == 31) wsum[t >> 5] = x;
    __syncthreads();
    if (t < 32) {
        int s = wsum[t];
#pragma unroll
        for (int o = 1; o < 32; o <<= 1) {
            int y = __shfl_up_sync(0xffffffffu, s, o);
            if (t >= o) s += y;
        }
        wsum[t] = s;
    }
    __syncthreads();
    int base = (t >= 32) ? wsum[(t >> 5) - 1] : 0;
    int inc = x + base;
    if (i < n) incl[i] = inc;
    if (t == 1023) btot[blockIdx.x] = inc;
}

// ---- pass2: exclusive scan of <=64 block totals (in place) ----
__global__ void scan_pass2(int* __restrict__ btot, int nb) {
    __shared__ int s[64];
    int t = threadIdx.x;
    s[t] = (t < nb) ? btot[t] : 0;
    __syncthreads();
#pragma unroll
    for (int o = 1; o < 64; o <<= 1) {
        int v = (t >= o) ? s[t - o] : 0;
        __syncthreads();
        s[t] += v;
        __syncthreads();
    }
    if (t < nb) btot[t] = t ? s[t - 1] : 0;
}

// ---- pass3: rp/cur = block offset + inclusive - deg ----
__global__ void scan_pass3(const int* __restrict__ incl, const int* __restrict__ deg,
                           const int* __restrict__ btot, int* __restrict__ rp,
                           int* __restrict__ cur, int n) {
    int i = blockIdx.x * 1024 + threadIdx.x;
    if (i < n) {
        int r = btot[blockIdx.x] + incl[i] - deg[i];
        rp[i] = r;
        cur[i] = r;
    }
}

__global__ void fill_kernel(const int* __restrict__ src, const int* __restrict__ dst,
                            int* __restrict__ cur, int* __restrict__ es, int E) {
    int e = blockIdx.x * blockDim.x + threadIdx.x;
    if (e < E) {
        int p = atomicAdd(&cur[dst[e]], 1);
        es[p] = src[e];
    }
}

// one warp per dst node; 4-way unrolled gather with 4 accumulators (4x MLP)
__global__ void agg_kernel(const float* __restrict__ h, const int* __restrict__ rp,
                           const int* __restrict__ deg, const int* __restrict__ es,
                           float* __restrict__ hn, int ndst) {
    int lane = threadIdx.x & 31;
    int w = (blockIdx.x * blockDim.x + threadIdx.x) >> 5;
    if (w >= ndst) return;
    int start = rp[w];
    int cnt = deg[w];
    float4 a0 = make_float4(0.f, 0.f, 0.f, 0.f);
    float4 a1 = make_float4(0.f, 0.f, 0.f, 0.f);
    float4 a2 = make_float4(0.f, 0.f, 0.f, 0.f);
    float4 a3 = make_float4(0.f, 0.f, 0.f, 0.f);
    const float4* h4 = reinterpret_cast<const float4*>(h);
    for (int base = 0; base < cnt; base += 32) {
        int n = min(32, cnt - base);
        int sidx = (lane < n) ? es[start + base + lane] : 0;
        int j = 0;
        for (; j + 4 <= n; j += 4) {
            int s0 = __shfl_sync(0xffffffffu, sidx, j);
            int s1 = __shfl_sync(0xffffffffu, sidx, j + 1);
            int s2 = __shfl_sync(0xffffffffu, sidx, j + 2);
            int s3 = __shfl_sync(0xffffffffu, sidx, j + 3);
            float4 v0 = h4[(size_t)s0 * 32 + lane];
            float4 v1 = h4[(size_t)s1 * 32 + lane];
            float4 v2 = h4[(size_t)s2 * 32 + lane];
            float4 v3 = h4[(size_t)s3 * 32 + lane];
            a0.x += v0.x; a0.y += v0.y; a0.z += v0.z; a0.w += v0.w;
            a1.x += v1.x; a1.y += v1.y; a1.z += v1.z; a1.w += v1.w;
            a2.x += v2.x; a2.y += v2.y; a2.z += v2.z; a2.w += v2.w;
            a3.x += v3.x; a3.y += v3.y; a3.z += v3.z; a3.w += v3.w;
        }
        for (; j < n; j++) {
            int s0 = __shfl_sync(0xffffffffu, sidx, j);
            float4 v0 = h4[(size_t)s0 * 32 + lane];
            a0.x += v0.x; a0.y += v0.y; a0.z += v0.z; a0.w += v0.w;
        }
    }
    float inv = 1.0f / (float)max(cnt, 1);
    reinterpret_cast<float4*>(hn)[(size_t)w * 32 + lane] =
        make_float4((a0.x + a1.x + a2.x + a3.x) * inv, (a0.y + a1.y + a2.y + a3.y) * inv,
                    (a0.z + a1.z + a2.z + a3.z) * inv, (a0.w + a1.w + a2.w + a3.w) * inv);
}

// ---------------- launch ----------------
extern "C" void kernel_launch(void* const* d_in, const int* in_sizes, int n_in,
                              void* d_out, int out_size) {
    const float* feat    = (const float*)d_in[0];
    const int*   src0    = (const int*)d_in[1];
    const int*   dst0    = (const int*)d_in[2];
    const int*   src1    = (const int*)d_in[3];
    const int*   dst1    = (const int*)d_in[4];
    const float* W_init  = (const float*)d_in[5];
    const float* b_init  = (const float*)d_in[6];
    const float* W_self  = (const float*)d_in[7];
    const float* b_self  = (const float*)d_in[8];
    const float* W_neigh = (const float*)d_in[9];
    const float* b_neigh = (const float*)d_in[10];
    float* out = (float*)d_out;

    float *h0, *h1, *hn0, *hn1;
    __nv_bfloat16 *WiH, *WiL, *WsH, *WsL, *WnH, *WnL;
    int *deg0, *rp0, *cur0, *es0, *deg1, *rp1, *cur1, *es1, *incl, *btot;
    cudaGetSymbolAddress((void**)&h0,  g_h0);
    cudaGetSymbolAddress((void**)&h1,  g_h1);
    cudaGetSymbolAddress((void**)&hn0, g_hn0);
    cudaGetSymbolAddress((void**)&hn1, g_hn1);
    cudaGetSymbolAddress((void**)&WiH, g_WiH);
    cudaGetSymbolAddress((void**)&WiL, g_WiL);
    cudaGetSymbolAddress((void**)&WsH, g_WsH);
    cudaGetSymbolAddress((void**)&WsL, g_WsL);
    cudaGetSymbolAddress((void**)&WnH, g_WnH);
    cudaGetSymbolAddress((void**)&WnL, g_WnL);
    cudaGetSymbolAddress((void**)&deg0, g_deg0);
    cudaGetSymbolAddress((void**)&rp0,  g_rp0);
    cudaGetSymbolAddress((void**)&cur0, g_cur0);
    cudaGetSymbolAddress((void**)&es0,  g_es0);
    cudaGetSymbolAddress((void**)&deg1, g_deg1);
    cudaGetSymbolAddress((void**)&rp1,  g_rp1);
    cudaGetSymbolAddress((void**)&cur1, g_cur1);
    cudaGetSymbolAddress((void**)&es1,  g_es1);
    cudaGetSymbolAddress((void**)&incl, g_incl);
    cudaGetSymbolAddress((void**)&btot, g_btot);

    cudaFuncSetAttribute(gemm_mma<true, false>,
                         cudaFuncAttributeMaxDynamicSharedMemorySize, SMEM_TOTAL);
    cudaFuncSetAttribute(gemm_mma<true, true>,
                         cudaFuncAttributeMaxDynamicSharedMemorySize, SMEM_TOTAL);
    cudaFuncSetAttribute(gemm_mma<false, true>,
                         cudaFuncAttributeMaxDynamicSharedMemorySize, SMEM_TOTAL);

    const int NB0 = (N_DST0 + 1023) / 1024;   // 49
    const int NB1 = (N_DST1 + 1023) / 1024;   // 10

    // weight images (Wt bf16 hi/lo), all three in one launch
    wprep_kernel<<<192, 256>>>(W_init, W_self, W_neigh, WiH, WiL, WsH, WsL, WnH, WnL);

    // h0 = relu(feat @ Wi + bi)
    gemm_mma<true, false><<<(N_SRC0 + 63) / 64, 128, SMEM_TOTAL>>>(
        feat, nullptr, WiH, WiL, nullptr, nullptr, b_init, nullptr, h0, N_SRC0);

    // layer 0 graph: CSR build + mean aggregate
    cudaMemsetAsync(deg0, 0, N_DST0 * sizeof(int), 0);
    hist_kernel<<<(E0 + 255) / 256, 256>>>(dst0, deg0, E0);
    scan_pass1<<<NB0, 1024>>>(deg0, incl, btot, N_DST0);
    scan_pass2<<<1, 64>>>(btot, NB0);
    scan_pass3<<<NB0, 1024>>>(incl, deg0, btot, rp0, cur0, N_DST0);
    fill_kernel<<<(E0 + 255) / 256, 256>>>(src0, dst0, cur0, es0, E0);
    agg_kernel<<<N_DST0 / 8, 256>>>(h0, rp0, deg0, es0, hn0, N_DST0);

    // h1 = relu(h0[:50000] @ Ws + hn0 @ Wn + bs + bn)
    gemm_mma<true, true><<<(N_DST0 + 63) / 64, 128, SMEM_TOTAL>>>(
        h0, hn0, WsH, WsL, WnH, WnL, b_self, b_neigh, h1, N_DST0);

    // layer 1 graph
    cudaMemsetAsync(deg1, 0, N_DST1 * sizeof(int), 0);
    hist_kernel<<<(E1 + 255) / 256, 256>>>(dst1, deg1, E1);
    scan_pass1<<<NB1, 1024>>>(deg1, incl, btot, N_DST1);
    scan_pass2<<<1, 64>>>(btot, NB1);
    scan_pass3<<<NB1, 1024>>>(incl, deg1, btot, rp1, cur1, N_DST1);
    fill_kernel<<<(E1 + 255) / 256, 256>>>(src1, dst1, cur1, es1, E1);
    agg_kernel<<<N_DST1 / 8, 256>>>(h1, rp1, deg1, es1, hn1, N_DST1);

    // out = h1[:10000] @ Ws + hn1 @ Wn + bs + bn  (no relu)
    gemm_mma<false, true><<<(N_DST1 + 63) / 64, 128, SMEM_TOTAL>>>(
        h1, hn1, WsH, WsL, WnH, WnL, b_self, b_neigh, out, N_DST1);
}

// round 6
// speedup vs baseline: 2.3200x; 1.0568x over previous
#include <cuda_runtime.h>
#include <cuda_bf16.h>
#include <cstdint>

// ---------------- problem sizes ----------------
#define N_SRC0 200000
#define N_DST0 50000
#define N_DST1 10000
#define E0     800000
#define E1     160000
#define D      128

// ---------------- scratch (device globals; no allocs allowed) ----------------
__device__ float g_h0[(size_t)N_SRC0 * D];
__device__ float g_h1[(size_t)N_DST0 * D];
__device__ float g_hn0[(size_t)N_DST0 * D];
__device__ float g_hn1[(size_t)N_DST1 * D];
// transposed bf16 weight images Wt[n][k] = W[k][n], hi/lo split
__device__ __align__(16) __nv_bfloat16 g_WiH[16384], g_WiL[16384];
__device__ __align__(16) __nv_bfloat16 g_WsH[16384], g_WsL[16384];
__device__ __align__(16) __nv_bfloat16 g_WnH[16384], g_WnL[16384];
__device__ int g_deg0[N_DST0], g_rp0[N_DST0], g_cur0[N_DST0];
__device__ int g_deg1[N_DST1], g_rp1[N_DST1], g_cur1[N_DST1];
__device__ int g_es0[E0], g_es1[E1];
__device__ int g_incl[N_DST0];       // scan temp (reused; serialized on side stream)
__device__ int g_btot[64];

// ---------------- helpers ----------------
__device__ __forceinline__ uint32_t smem_to_u32(const void* p) {
    uint32_t a;
    asm("{ .reg .u64 t; cvta.to.shared.u64 t, %1; cvt.u32.u64 %0, t; }" : "=r"(a) : "l"(p));
    return a;
}

#define LDMATRIX_X4(r0, r1, r2, r3, addr) \
    asm volatile("ldmatrix.sync.aligned.m8n8.x4.shared.b16 {%0,%1,%2,%3}, [%4];" \
                 : "=r"(r0), "=r"(r1), "=r"(r2), "=r"(r3) : "r"(addr))

#define MMA_BF16(d, a, bv0, bv1) \
    asm volatile("mma.sync.aligned.m16n8k16.row.col.f32.bf16.bf16.f32 " \
                 "{%0,%1,%2,%3}, {%4,%5,%6,%7}, {%8,%9}, {%0,%1,%2,%3};" \
                 : "+f"((d)[0]), "+f"((d)[1]), "+f"((d)[2]), "+f"((d)[3]) \
                 : "r"((a)[0]), "r"((a)[1]), "r"((a)[2]), "r"((a)[3]), \
                   "r"(bv0), "r"(bv1))

#define CP_ASYNC16(dst, src) \
    asm volatile("cp.async.cg.shared.global [%0], [%1], 16;" :: "r"(dst), "l"(src))
#define CP_COMMIT() asm volatile("cp.async.commit_group;")
#define CP_WAIT0()  asm volatile("cp.async.wait_group 0;" ::: "memory")

// ---------------- weight image prep (one launch for all 3) ----------------
__global__ void wprep_kernel(const float* __restrict__ Wi, const float* __restrict__ Ws,
                             const float* __restrict__ Wn,
                             __nv_bfloat16* __restrict__ WiH, __nv_bfloat16* __restrict__ WiL,
                             __nv_bfloat16* __restrict__ WsH, __nv_bfloat16* __restrict__ WsL,
                             __nv_bfloat16* __restrict__ WnH, __nv_bfloat16* __restrict__ WnL) {
    int bid = blockIdx.x;
    const float* W = (bid < 64) ? Wi : (bid < 128) ? Ws : Wn;
    __nv_bfloat16* H = (bid < 64) ? WiH : (bid < 128) ? WsH : WnH;
    __nv_bfloat16* L = (bid < 64) ? WiL : (bid < 128) ? WsL : WnL;
    int idx = (bid & 63) * 256 + threadIdx.x;   // 0..16383
    int n = idx >> 7, k = idx & 127;
    float w = W[k * 128 + n];
    __nv_bfloat16 h = __float2bfloat16(w);
    __nv_bfloat16 l = __float2bfloat16(w - __bfloat162float(h));
    H[idx] = h;
    L[idx] = l;
}

// ---------------- mma.sync GEMM ----------------
#define SA 136
#define OFF_BIAS 0
#define OFF_AH   512
#define OFF_AL   (OFF_AH + 64 * SA * 2)
#define OFF_WH   (OFF_AL + 64 * SA * 2)
#define OFF_WL   (OFF_WH + 128 * SA * 2)
#define SMEM_TOTAL (OFF_WL + 128 * SA * 2)

template <bool RELU, bool DUAL>
__global__ void __launch_bounds__(128)
gemm_mma(const float* __restrict__ A0, const float* __restrict__ A1,
         const __nv_bfloat16* __restrict__ W0h, const __nv_bfloat16* __restrict__ W0l,
         const __nv_bfloat16* __restrict__ W1h, const __nv_bfloat16* __restrict__ W1l,
         const float* __restrict__ b0, const float* __restrict__ b1,
         float* __restrict__ out, int M)
{
    extern __shared__ char smem[];
    float* sbias = reinterpret_cast<float*>(smem + OFF_BIAS);
    const uint32_t sb = smem_to_u32(smem);
    const int tid = threadIdx.x;
    const int wid = tid >> 5;
    const int lane = tid & 31;
    const int warp_m = wid & 1;
    const int warp_n = wid >> 1;
    const int rowBase = blockIdx.x * 64;

    if (tid < 128) {
        float b = b0[tid];
        if (DUAL) b += b1[tid];
        sbias[tid] = b;
    }

    float acc[2][8][4];
#pragma unroll
    for (int i = 0; i < 2; i++)
#pragma unroll
        for (int j = 0; j < 8; j++)
#pragma unroll
            for (int r = 0; r < 4; r++) acc[i][j][r] = 0.f;

    const int tl = lane >> 3, trow = lane & 7;
    uint32_t aoff[2], boff[4];
#pragma unroll
    for (int mi = 0; mi < 2; mi++) {
        int row = warp_m * 32 + mi * 16 + trow + (tl & 1) * 8;
        int col = (tl >> 1) * 8;
        aoff[mi] = (uint32_t)(row * SA + col) * 2;
    }
#pragma unroll
    for (int nh = 0; nh < 4; nh++) {
        int n = warp_n * 64 + nh * 16 + (tl >> 1) * 8 + trow;
        int col = (tl & 1) * 8;
        boff[nh] = (uint32_t)(n * SA + col) * 2;
    }

    const int npass = DUAL ? 2 : 1;
#pragma unroll 1
    for (int pass = 0; pass < npass; ++pass) {
        const float* A = pass ? A1 : A0;
        const __nv_bfloat16* Wh = pass ? W1h : W0h;
        const __nv_bfloat16* Wl = pass ? W1l : W0l;

        {
            const uint4* gh = reinterpret_cast<const uint4*>(Wh);
            const uint4* gl = reinterpret_cast<const uint4*>(Wl);
#pragma unroll
            for (int it = 0; it < 16; it++) {
                int idx = it * 128 + tid;
                int r = idx >> 4, wg = idx & 15;
                uint32_t d = (uint32_t)(r * SA + wg * 8) * 2;
                CP_ASYNC16(sb + OFF_WH + d, gh + idx);
                CP_ASYNC16(sb + OFF_WL + d, gl + idx);
            }
            CP_COMMIT();
        }
#pragma unroll
        for (int it = 0; it < 16; it++) {
            int e = it * 128 + tid;
            int row = e >> 5, c4 = e & 31;
            int grow = rowBase + row;
            float4 v = make_float4(0.f, 0.f, 0.f, 0.f);
            if (grow < M)
                v = *reinterpret_cast<const float4*>(A + (size_t)grow * D + c4 * 4);
            __nv_bfloat162 h01 = __float22bfloat162_rn(make_float2(v.x, v.y));
            __nv_bfloat162 h23 = __float22bfloat162_rn(make_float2(v.z, v.w));
            float2 f01 = __bfloat1622float2(h01);
            float2 f23 = __bfloat1622float2(h23);
            __nv_bfloat162 l01 = __float22bfloat162_rn(make_float2(v.x - f01.x, v.y - f01.y));
            __nv_bfloat162 l23 = __float22bfloat162_rn(make_float2(v.z - f23.x, v.w - f23.y));
            uint32_t d = (uint32_t)(row * SA + c4 * 4) * 2;
            uint2 hw, lw;
            hw.x = *reinterpret_cast<uint32_t*>(&h01);
            hw.y = *reinterpret_cast<uint32_t*>(&h23);
            lw.x = *reinterpret_cast<uint32_t*>(&l01);
            lw.y = *reinterpret_cast<uint32_t*>(&l23);
            *reinterpret_cast<uint2*>(smem + OFF_AH + d) = hw;
            *reinterpret_cast<uint2*>(smem + OFF_AL + d) = lw;
        }
        CP_WAIT0();
        __syncthreads();

#pragma unroll
        for (int ks = 0; ks < 8; ks++) {
            const uint32_t kb = ks * 32;
            uint32_t bh[16], bl[16];
#pragma unroll
            for (int nh = 0; nh < 4; nh++) {
                LDMATRIX_X4(bh[nh * 4], bh[nh * 4 + 1], bh[nh * 4 + 2], bh[nh * 4 + 3],
                            sb + OFF_WH + boff[nh] + kb);
                LDMATRIX_X4(bl[nh * 4], bl[nh * 4 + 1], bl[nh * 4 + 2], bl[nh * 4 + 3],
                            sb + OFF_WL + boff[nh] + kb);
            }
#pragma unroll
            for (int mi = 0; mi < 2; mi++) {
                uint32_t ah[4], al[4];
                LDMATRIX_X4(ah[0], ah[1], ah[2], ah[3], sb + OFF_AH + aoff[mi] + kb);
                LDMATRIX_X4(al[0], al[1], al[2], al[3], sb + OFF_AL + aoff[mi] + kb);
#pragma unroll
                for (int nj = 0; nj < 8; nj++) {
                    int bi = (nj >> 1) * 4 + (nj & 1) * 2;
                    MMA_BF16(acc[mi][nj], ah, bh[bi], bh[bi + 1]);
                    MMA_BF16(acc[mi][nj], al, bh[bi], bh[bi + 1]);
                    MMA_BF16(acc[mi][nj], ah, bl[bi], bl[bi + 1]);
                }
            }
        }
        __syncthreads();
    }

    const int g = lane >> 2, t = lane & 3;
#pragma unroll
    for (int mi = 0; mi < 2; mi++) {
        int row0 = rowBase + warp_m * 32 + mi * 16 + g;
        int row1 = row0 + 8;
#pragma unroll
        for (int nj = 0; nj < 8; nj++) {
            int col = warp_n * 64 + nj * 8 + t * 2;
            float bx = sbias[col], by = sbias[col + 1];
            float2 v0 = make_float2(acc[mi][nj][0] + bx, acc[mi][nj][1] + by);
            float2 v1 = make_float2(acc[mi][nj][2] + bx, acc[mi][nj][3] + by);
            if (RELU) {
                v0.x = fmaxf(v0.x, 0.f); v0.y = fmaxf(v0.y, 0.f);
                v1.x = fmaxf(v1.x, 0.f); v1.y = fmaxf(v1.y, 0.f);
            }
            if (row0 < M)
                *reinterpret_cast<float2*>(out + (size_t)row0 * D + col) = v0;
            if (row1 < M)
                *reinterpret_cast<float2*>(out + (size_t)row1 * D + col) = v1;
        }
    }
}

// ---------------- graph CSR build + mean aggregation ----------------
__global__ void hist_kernel(const int* __restrict__ dst, int* __restrict__ deg, int E) {
    int e = blockIdx.x * blockDim.x + threadIdx.x;
    if (e < E) atomicAdd(&deg[dst[e]], 1);
}

__global__ void scan_pass1(const int* __restrict__ deg, int* __restrict__ incl,
                           int* __restrict__ btot, int n) {
    __shared__ int wsum[32];
    int t = threadIdx.x;
    int i = blockIdx.x * 1024 + t;
    int v = (i < n) ? deg[i] : 0;
    int x = v;
#pragma unroll
    for (int o = 1; o < 32; o <<= 1) {
        int y = __shfl_up_sync(0xffffffffu, x, o);
        if ((t & 31) >= o) x += y;
    }
    if ((t & 31) == 31) wsum[t >> 5] = x;
    __syncthreads();
    if (t < 32) {
        int s = wsum[t];
#pragma unroll
        for (int o = 1; o < 32; o <<= 1) {
            int y = __shfl_up_sync(0xffffffffu, s, o);
            if (t >= o) s += y;
        }
        wsum[t] = s;
    }
    __syncthreads();
    int base = (t >= 32) ? wsum[(t >> 5) - 1] : 0;
    int inc = x + base;
    if (i < n) incl[i] = inc;
    if (t == 1023) btot[blockIdx.x] = inc;
}

__global__ void scan_pass2(int* __restrict__ btot, int nb) {
    __shared__ int s[64];
    int t = threadIdx.x;
    s[t] = (t < nb) ? btot[t] : 0;
    __syncthreads();
#pragma unroll
    for (int o = 1; o < 64; o <<= 1) {
        int v = (t >= o) ? s[t - o] : 0;
        __syncthreads();
        s[t] += v;
        __syncthreads();
    }
    if (t < nb) btot[t] = t ? s[t - 1] : 0;
}

__global__ void scan_pass3(const int* __restrict__ incl, const int* __restrict__ deg,
                           const int* __restrict__ btot, int* __restrict__ rp,
                           int* __restrict__ cur, int n) {
    int i = blockIdx.x * 1024 + threadIdx.x;
    if (i < n) {
        int r = btot[blockIdx.x] + incl[i] - deg[i];
        rp[i] = r;
        cur[i] = r;
    }
}

__global__ void fill_kernel(const int* __restrict__ src, const int* __restrict__ dst,
                            int* __restrict__ cur, int* __restrict__ es, int E) {
    int e = blockIdx.x * blockDim.x + threadIdx.x;
    if (e < E) {
        int p = atomicAdd(&cur[dst[e]], 1);
        es[p] = src[e];
    }
}

// one warp per dst node; 4-way unrolled gather with 4 accumulators
__global__ void agg_kernel(const float* __restrict__ h, const int* __restrict__ rp,
                           const int* __restrict__ deg, const int* __restrict__ es,
                           float* __restrict__ hn, int ndst) {
    int lane = threadIdx.x & 31;
    int w = (blockIdx.x * blockDim.x + threadIdx.x) >> 5;
    if (w >= ndst) return;
    int start = rp[w];
    int cnt = deg[w];
    float4 a0 = make_float4(0.f, 0.f, 0.f, 0.f);
    float4 a1 = make_float4(0.f, 0.f, 0.f, 0.f);
    float4 a2 = make_float4(0.f, 0.f, 0.f, 0.f);
    float4 a3 = make_float4(0.f, 0.f, 0.f, 0.f);
    const float4* h4 = reinterpret_cast<const float4*>(h);
    for (int base = 0; base < cnt; base += 32) {
        int n = min(32, cnt - base);
        int sidx = (lane < n) ? es[start + base + lane] : 0;
        int j = 0;
        for (; j + 4 <= n; j += 4) {
            int s0 = __shfl_sync(0xffffffffu, sidx, j);
            int s1 = __shfl_sync(0xffffffffu, sidx, j + 1);
            int s2 = __shfl_sync(0xffffffffu, sidx, j + 2);
            int s3 = __shfl_sync(0xffffffffu, sidx, j + 3);
            float4 v0 = h4[(size_t)s0 * 32 + lane];
            float4 v1 = h4[(size_t)s1 * 32 + lane];
            float4 v2 = h4[(size_t)s2 * 32 + lane];
            float4 v3 = h4[(size_t)s3 * 32 + lane];
            a0.x += v0.x; a0.y += v0.y; a0.z += v0.z; a0.w += v0.w;
            a1.x += v1.x; a1.y += v1.y; a1.z += v1.z; a1.w += v1.w;
            a2.x += v2.x; a2.y += v2.y; a2.z += v2.z; a2.w += v2.w;
            a3.x += v3.x; a3.y += v3.y; a3.z += v3.z; a3.w += v3.w;
        }
        for (; j < n; j++) {
            int s0 = __shfl_sync(0xffffffffu, sidx, j);
            float4 v0 = h4[(size_t)s0 * 32 + lane];
            a0.x += v0.x; a0.y += v0.y; a0.z += v0.z; a0.w += v0.w;
        }
    }
    float inv = 1.0f / (float)max(cnt, 1);
    reinterpret_cast<float4*>(hn)[(size_t)w * 32 + lane] =
        make_float4((a0.x + a1.x + a2.x + a3.x) * inv, (a0.y + a1.y + a2.y + a3.y) * inv,
                    (a0.z + a1.z + a2.z + a3.z) * inv, (a0.w + a1.w + a2.w + a3.w) * inv);
}

// ---------------- launch ----------------
extern "C" void kernel_launch(void* const* d_in, const int* in_sizes, int n_in,
                              void* d_out, int out_size) {
    const float* feat    = (const float*)d_in[0];
    const int*   src0    = (const int*)d_in[1];
    const int*   dst0    = (const int*)d_in[2];
    const int*   src1    = (const int*)d_in[3];
    const int*   dst1    = (const int*)d_in[4];
    const float* W_init  = (const float*)d_in[5];
    const float* b_init  = (const float*)d_in[6];
    const float* W_self  = (const float*)d_in[7];
    const float* b_self  = (const float*)d_in[8];
    const float* W_neigh = (const float*)d_in[9];
    const float* b_neigh = (const float*)d_in[10];
    float* out = (float*)d_out;

    float *h0, *h1, *hn0, *hn1;
    __nv_bfloat16 *WiH, *WiL, *WsH, *WsL, *WnH, *WnL;
    int *deg0, *rp0, *cur0, *es0, *deg1, *rp1, *cur1, *es1, *incl, *btot;
    cudaGetSymbolAddress((void**)&h0,  g_h0);
    cudaGetSymbolAddress((void**)&h1,  g_h1);
    cudaGetSymbolAddress((void**)&hn0, g_hn0);
    cudaGetSymbolAddress((void**)&hn1, g_hn1);
    cudaGetSymbolAddress((void**)&WiH, g_WiH);
    cudaGetSymbolAddress((void**)&WiL, g_WiL);
    cudaGetSymbolAddress((void**)&WsH, g_WsH);
    cudaGetSymbolAddress((void**)&WsL, g_WsL);
    cudaGetSymbolAddress((void**)&WnH, g_WnH);
    cudaGetSymbolAddress((void**)&WnL, g_WnL);
    cudaGetSymbolAddress((void**)&deg0, g_deg0);
    cudaGetSymbolAddress((void**)&rp0,  g_rp0);
    cudaGetSymbolAddress((void**)&cur0, g_cur0);
    cudaGetSymbolAddress((void**)&es0,  g_es0);
    cudaGetSymbolAddress((void**)&deg1, g_deg1);
    cudaGetSymbolAddress((void**)&rp1,  g_rp1);
    cudaGetSymbolAddress((void**)&cur1, g_cur1);
    cudaGetSymbolAddress((void**)&es1,  g_es1);
    cudaGetSymbolAddress((void**)&incl, g_incl);
    cudaGetSymbolAddress((void**)&btot, g_btot);

    cudaFuncSetAttribute(gemm_mma<true, false>,
                         cudaFuncAttributeMaxDynamicSharedMemorySize, SMEM_TOTAL);
    cudaFuncSetAttribute(gemm_mma<true, true>,
                         cudaFuncAttributeMaxDynamicSharedMemorySize, SMEM_TOTAL);
    cudaFuncSetAttribute(gemm_mma<false, true>,
                         cudaFuncAttributeMaxDynamicSharedMemorySize, SMEM_TOTAL);

    // side stream + events (created once on the first, non-captured call)
    static cudaStream_t sA = nullptr;
    static cudaEvent_t evFork = nullptr, ev0 = nullptr, ev1 = nullptr;
    if (!sA) {
        cudaStreamCreateWithFlags(&sA, cudaStreamNonBlocking);
        cudaEventCreateWithFlags(&evFork, cudaEventDisableTiming);
        cudaEventCreateWithFlags(&ev0, cudaEventDisableTiming);
        cudaEventCreateWithFlags(&ev1, cudaEventDisableTiming);
    }

    const int NB0 = (N_DST0 + 1023) / 1024;   // 49
    const int NB1 = (N_DST1 + 1023) / 1024;   // 10

    // ---- fork: CSR builds run on sA concurrent with wprep/gemm1/gemm2 ----
    cudaEventRecord(evFork, 0);
    cudaStreamWaitEvent(sA, evFork, 0);

    // side stream: CSR layer 0 then layer 1 (shared scan temps serialize them)
    cudaMemsetAsync(deg0, 0, N_DST0 * sizeof(int), sA);
    hist_kernel<<<(E0 + 255) / 256, 256, 0, sA>>>(dst0, deg0, E0);
    scan_pass1<<<NB0, 1024, 0, sA>>>(deg0, incl, btot, N_DST0);
    scan_pass2<<<1, 64, 0, sA>>>(btot, NB0);
    scan_pass3<<<NB0, 1024, 0, sA>>>(incl, deg0, btot, rp0, cur0, N_DST0);
    fill_kernel<<<(E0 + 255) / 256, 256, 0, sA>>>(src0, dst0, cur0, es0, E0);
    cudaEventRecord(ev0, sA);
    cudaMemsetAsync(deg1, 0, N_DST1 * sizeof(int), sA);
    hist_kernel<<<(E1 + 255) / 256, 256, 0, sA>>>(dst1, deg1, E1);
    scan_pass1<<<NB1, 1024, 0, sA>>>(deg1, incl, btot, N_DST1);
    scan_pass2<<<1, 64, 0, sA>>>(btot, NB1);
    scan_pass3<<<NB1, 1024, 0, sA>>>(incl, deg1, btot, rp1, cur1, N_DST1);
    fill_kernel<<<(E1 + 255) / 256, 256, 0, sA>>>(src1, dst1, cur1, es1, E1);
    cudaEventRecord(ev1, sA);

    // main stream: weight prep + fc_init GEMM
    wprep_kernel<<<192, 256>>>(W_init, W_self, W_neigh, WiH, WiL, WsH, WsL, WnH, WnL);
    gemm_mma<true, false><<<(N_SRC0 + 63) / 64, 128, SMEM_TOTAL>>>(
        feat, nullptr, WiH, WiL, nullptr, nullptr, b_init, nullptr, h0, N_SRC0);

    // join CSR0, then aggregate + layer-0 GEMM
    cudaStreamWaitEvent(0, ev0, 0);
    agg_kernel<<<N_DST0 / 8, 256>>>(h0, rp0, deg0, es0, hn0, N_DST0);
    gemm_mma<true, true><<<(N_DST0 + 63) / 64, 128, SMEM_TOTAL>>>(
        h0, hn0, WsH, WsL, WnH, WnL, b_self, b_neigh, h1, N_DST0);

    // join CSR1, then aggregate + layer-1 GEMM
    cudaStreamWaitEvent(0, ev1, 0);
    agg_kernel<<<N_DST1 / 8, 256>>>(h1, rp1, deg1, es1, hn1, N_DST1);
    gemm_mma<false, true><<<(N_DST1 + 63) / 64, 128, SMEM_TOTAL>>>(
        h1, hn1, WsH, WsL, WnH, WnL, b_self, b_neigh, out, N_DST1);
}